// round 12
// baseline (speedup 1.0000x reference)
#include <cuda_runtime.h>
#include <cuda_bf16.h>
#include <mma.h>
#include <cstddef>
#include <cstdint>

using namespace nvcuda;

// Problem constants
#define B_ 8
#define N_ 784
#define C_ 768
#define H_ 16
#define D_ 48
#define S_ 28
#define M_ (B_ * N_)          // 6272 rows
#define BH_ (B_ * H_)         // 128
#define SCALE_ 0.14433756729740643f  // 48^-0.5

__device__ __forceinline__ uint32_t smem_u32(const void* p) {
    uint32_t a;
    asm("{ .reg .u64 t; cvta.to.shared.u64 t, %1; cvt.u32.u64 %0, t; }" : "=r"(a) : "l"(p));
    return a;
}
#define CP16(dst, src) \
    asm volatile("cp.async.ca.shared.global [%0], [%1], 16;" :: "r"(dst), "l"(src))
#define CP_COMMIT() asm volatile("cp.async.commit_group;")
#define CP_WAIT1()  asm volatile("cp.async.wait_group 1;")
#define CP_WAIT0()  asm volatile("cp.async.wait_group 0;")

__device__ __forceinline__ uint32_t pack_bf16x2(float lo, float hi) {
    uint32_t r;
    asm("cvt.rn.bf16x2.f32 %0, %1, %2;" : "=r"(r) : "f"(hi), "f"(lo));
    return r;
}
__device__ __forceinline__ float bfx2_lo(uint32_t pk) { return __uint_as_float(pk << 16); }
__device__ __forceinline__ float bfx2_hi(uint32_t pk) { return __uint_as_float(pk & 0xFFFF0000u); }

// ---------------- scratch (device globals; no allocation allowed) ----------
__device__ float g_pos[(size_t)H_ * N_ * N_];  // softmaxed positional scores
__device__ float g_psum[(size_t)BH_ * 7 * N_]; // per-colblock exp row sums
__device__ __align__(16) __nv_bfloat16 g_xh[(size_t)M_ * C_], g_xl[(size_t)M_ * C_];
__device__ __align__(16) __nv_bfloat16 g_wh[4 * (size_t)C_ * C_], g_wl[4 * (size_t)C_ * C_];
__device__ __align__(16) __nv_bfloat16 g_oh[(size_t)M_ * C_], g_ol[(size_t)M_ * C_];
// per-head split operands: [bh][n][48]
__device__ __align__(16) __nv_bfloat16 g_qh[(size_t)BH_ * N_ * D_], g_ql[(size_t)BH_ * N_ * D_];
__device__ __align__(16) __nv_bfloat16 g_kh[(size_t)BH_ * N_ * D_], g_kl[(size_t)BH_ * N_ * D_];
__device__ __align__(16) __nv_bfloat16 g_vh[(size_t)BH_ * N_ * D_], g_vl[(size_t)BH_ * N_ * D_];

// ---------------- fp32 -> (hi, lo) bf16 split kernels -----------------------
__device__ __forceinline__ void split4(const float* src, __nv_bfloat16* hi,
                                       __nv_bfloat16* lo, size_t i4) {
    float4 v = *(const float4*)(src + i4 * 4);
    uint32_t h01 = pack_bf16x2(v.x, v.y);
    uint32_t h23 = pack_bf16x2(v.z, v.w);
    uint32_t l01 = pack_bf16x2(v.x - bfx2_lo(h01), v.y - bfx2_hi(h01));
    uint32_t l23 = pack_bf16x2(v.z - bfx2_lo(h23), v.w - bfx2_hi(h23));
    *(uint2*)(hi + i4 * 4) = make_uint2(h01, h23);
    *(uint2*)(lo + i4 * 4) = make_uint2(l01, l23);
}

__global__ void __launch_bounds__(256) split_x(const float* __restrict__ x) {
    size_t i = (size_t)blockIdx.x * 256 + threadIdx.x;
    if (i < (size_t)M_ * C_ / 4) split4(x, g_xh, g_xl, i);
}
__global__ void __launch_bounds__(256) split_w(const float* __restrict__ Wq,
                                               const float* __restrict__ Wk,
                                               const float* __restrict__ Wv,
                                               const float* __restrict__ Wp) {
    const int z = blockIdx.y;
    const float* src = (z == 0) ? Wq : (z == 1) ? Wk : (z == 2) ? Wv : Wp;
    size_t i = (size_t)blockIdx.x * 256 + threadIdx.x;
    if (i < (size_t)C_ * C_ / 4)
        split4(src, g_wh + (size_t)z * C_ * C_, g_wl + (size_t)z * C_ * C_, i);
}

// ---------------- positional scores: warp-per-row softmax -------------------
__global__ void __launch_bounds__(256) pos_kernel(const float* __restrict__ W_pos,
                                                  const float* __restrict__ b_pos) {
    const int h = blockIdx.y;
    const int n = blockIdx.x * 8 + (threadIdx.x >> 5);
    const int lid = threadIdx.x & 31;
    const float w0 = W_pos[h * 3 + 0];
    const float w1 = W_pos[h * 3 + 1];
    const float w2 = W_pos[h * 3 + 2];
    const float bp = b_pos[h];
    const int i1 = n / S_;
    const int j1 = n % S_;

    float buf[25];
    float mx = -1e30f;
    int m = lid;
    int mi = lid / S_, mj = lid % S_;
#pragma unroll
    for (int t = 0; t < 25; t++) {
        if (m < N_) {
            const float dx = (float)(mj - j1);
            const float dy = (float)(mi - i1);
            const float l = w0 * dx + w1 * dy + w2 * (dx * dx + dy * dy) + bp;
            buf[t] = l;
            mx = fmaxf(mx, l);
        } else buf[t] = -1e30f;
        m += 32;
        mi += 1; mj += 4;
        if (mj >= S_) { mj -= S_; mi += 1; }
    }
#pragma unroll
    for (int off = 16; off > 0; off >>= 1)
        mx = fmaxf(mx, __shfl_xor_sync(0xffffffffu, mx, off));

    float sum = 0.f;
#pragma unroll
    for (int t = 0; t < 25; t++) {
        const float e = __expf(buf[t] - mx);
        buf[t] = e;
        sum += e;
    }
#pragma unroll
    for (int off = 16; off > 0; off >>= 1)
        sum += __shfl_xor_sync(0xffffffffu, sum, off);
    const float inv = 1.f / sum;

    float* row = g_pos + ((size_t)h * N_ + n) * N_;
    m = lid;
#pragma unroll
    for (int t = 0; t < 25; t++) {
        if (m < N_) row[m] = buf[t] * inv;
        m += 32;
    }
}

// ================= wmma split-bf16 GEMM, cp.async double buffered ===========
// C[i,j] = sum_k A[i,k]*B[j,k]  via  Ah*Bh + Ah*Bl + Al*Bh  (fp32 accum)
#define TSTR 40                   // smem tile stride (bf16 elems)
#define TCB 40960                 // bytes per stage (4 arrays x 10240)
#define TC_SMEM (2 * TCB + 8192)  // + stage floats

__global__ void __launch_bounds__(256) tc_gemm(int mode, float* __restrict__ outC,
                                               float* __restrict__ out_v,
                                               const float* __restrict__ bias) {
    extern __shared__ char gsm[];
    float (*stage)[256] = (float(*)[256])(gsm + 2 * TCB);
    const uint32_t sb = smem_u32(gsm);

    const int tid = threadIdx.x;
    const int w = tid >> 5;
    const int lid = tid & 31;
    const int wm = w & 1;          // 0..1  (64 rows each)
    const int wn = w >> 1;         // 0..3  (32 cols each)
    const int j0 = blockIdx.x * 128;
    const int i0 = blockIdx.y * 128;
    const int z = blockIdx.z;

    const __nv_bfloat16 *Ah, *Al, *Bh, *Bl;
    if (mode == 0) {
        Ah = g_xh; Al = g_xl;
        Bh = g_wh + (size_t)z * C_ * C_; Bl = g_wl + (size_t)z * C_ * C_;
    } else {
        Ah = g_oh; Al = g_ol;
        Bh = g_wh + (size_t)3 * C_ * C_; Bl = g_wl + (size_t)3 * C_ * C_;
    }

    const int prow = tid >> 2;            // 0..63
    const int pseg = (tid & 3) * 8;       // bf16 offset within 32

    wmma::fragment<wmma::accumulator, 16, 16, 16, float> acc[4][2];
#pragma unroll
    for (int i = 0; i < 4; i++)
#pragma unroll
        for (int j = 0; j < 2; j++) wmma::fill_fragment(acc[i][j], 0.f);

    auto issue = [&](int ch, int s) {
        const int koff = ch * 32 + pseg;
#pragma unroll
        for (int it = 0; it < 2; it++) {
            const int row = prow + it * 64;
            const uint32_t d = sb + s * TCB + (row * TSTR + pseg) * 2;
            CP16(d +     0, Ah + (size_t)(i0 + row) * C_ + koff);
            CP16(d + 10240, Al + (size_t)(i0 + row) * C_ + koff);
            CP16(d + 20480, Bh + (size_t)(j0 + row) * C_ + koff);
            CP16(d + 30720, Bl + (size_t)(j0 + row) * C_ + koff);
        }
        CP_COMMIT();
    };

    issue(0, 0);
    for (int ch = 0; ch < C_ / 32; ch++) {
        const int s = ch & 1;
        if (ch + 1 < C_ / 32) { issue(ch + 1, (ch + 1) & 1); CP_WAIT1(); }
        else                  { CP_WAIT0(); }
        __syncthreads();

        const __nv_bfloat16* bAh = (const __nv_bfloat16*)(gsm + s * TCB);
        const __nv_bfloat16* bAl = (const __nv_bfloat16*)(gsm + s * TCB + 10240);
        const __nv_bfloat16* bBh = (const __nv_bfloat16*)(gsm + s * TCB + 20480);
        const __nv_bfloat16* bBl = (const __nv_bfloat16*)(gsm + s * TCB + 30720);

#pragma unroll
        for (int ks = 0; ks < 2; ks++) {
            const int kk = ks * 16;
            wmma::fragment<wmma::matrix_a, 16, 16, 16, __nv_bfloat16, wmma::row_major> fah[4], fal[4];
            wmma::fragment<wmma::matrix_b, 16, 16, 16, __nv_bfloat16, wmma::col_major> fbh[2], fbl[2];
#pragma unroll
            for (int i = 0; i < 4; i++) {
                const int r = wm * 64 + i * 16;
                wmma::load_matrix_sync(fah[i], &bAh[r * TSTR + kk], TSTR);
                wmma::load_matrix_sync(fal[i], &bAl[r * TSTR + kk], TSTR);
            }
#pragma unroll
            for (int j = 0; j < 2; j++) {
                const int c = wn * 32 + j * 16;
                wmma::load_matrix_sync(fbh[j], &bBh[c * TSTR + kk], TSTR);
                wmma::load_matrix_sync(fbl[j], &bBl[c * TSTR + kk], TSTR);
            }
#pragma unroll
            for (int i = 0; i < 4; i++)
#pragma unroll
                for (int j = 0; j < 2; j++) {
                    wmma::mma_sync(acc[i][j], fah[i], fbh[j], acc[i][j]);
                    wmma::mma_sync(acc[i][j], fah[i], fbl[j], acc[i][j]);
                    wmma::mma_sync(acc[i][j], fal[i], fbh[j], acc[i][j]);
                }
        }
        __syncthreads();
    }

    if (mode == 1) {
#pragma unroll
        for (int i = 0; i < 4; i++) {
            const int row0 = i0 + wm * 64 + i * 16;
#pragma unroll
            for (int j = 0; j < 2; j++) {
                const int col0 = j0 + wn * 32 + j * 16;
                __syncwarp();
                wmma::store_matrix_sync(&stage[w][0], acc[i][j], 16, wmma::mem_row_major);
                __syncwarp();
#pragma unroll
                for (int tt = 0; tt < 8; tt++) {
                    const int idx = tt * 32 + lid;
                    const int r = idx >> 4;
                    const int c = idx & 15;
                    outC[(size_t)(row0 + r) * C_ + col0 + c] = stage[w][idx] + bias[col0 + c];
                }
            }
        }
        return;
    }

    // mode 0 epilogue: stage fragments, vectorized scatter to per-head splits
#pragma unroll
    for (int i = 0; i < 4; i++) {
        const int row0 = i0 + wm * 64 + i * 16;
#pragma unroll
        for (int j = 0; j < 2; j++) {
            const int col0 = j0 + wn * 32 + j * 16;
            __syncwarp();
            wmma::store_matrix_sync(&stage[w][0], acc[i][j], 16, wmma::mem_row_major);
            __syncwarp();
#pragma unroll
            for (int half = 0; half < 2; half++) {
                const int r = half * 8 + (lid >> 2);
                const int c4 = (lid & 3) * 4;
                float4 v4 = *(float4*)&stage[w][r * 16 + c4];
                const int grow = row0 + r;
                const int gcol = col0 + c4;                  // 4-col group, never crosses head
                const int b = grow / N_;
                const int n = grow % N_;
                const int h = gcol / D_;
                const int d = gcol % D_;
                const size_t dst = ((size_t)(b * H_ + h) * N_ + n) * D_ + d;
                if (z == 0) {
                    v4.x *= SCALE_; v4.y *= SCALE_; v4.z *= SCALE_; v4.w *= SCALE_;
                }
                const uint32_t h01 = pack_bf16x2(v4.x, v4.y);
                const uint32_t h23 = pack_bf16x2(v4.z, v4.w);
                const uint32_t l01 = pack_bf16x2(v4.x - bfx2_lo(h01), v4.y - bfx2_hi(h01));
                const uint32_t l23 = pack_bf16x2(v4.z - bfx2_lo(h23), v4.w - bfx2_hi(h23));
                __nv_bfloat16 *ph, *pl;
                if (z == 0)      { ph = g_qh; pl = g_ql; }
                else if (z == 1) { ph = g_kh; pl = g_kl; }
                else             { ph = g_vh; pl = g_vl; *(float4*)(out_v + dst) = v4; }
                *(uint2*)(ph + dst) = make_uint2(h01, h23);
                *(uint2*)(pl + dst) = make_uint2(l01, l23);
            }
        }
    }
}

// ================ QK^T wmma GEMM -> E = exp(score) + partial row sums =======
// QSTR=56: 112B row stride -> 16B-aligned uint4 stores AND conflict-free LDSM
#define QSTR 56
#define QTB (128 * QSTR * 2)            // 14336 bytes per tile
#define QK_SMEM (4 * QTB)               // 57344

__global__ void __launch_bounds__(256) qk_gemm(float* __restrict__ attn) {
    extern __shared__ char qsm[];
    __nv_bfloat16* sQh = (__nv_bfloat16*)qsm;
    __nv_bfloat16* sQl = (__nv_bfloat16*)(qsm + QTB);
    __nv_bfloat16* sKh = (__nv_bfloat16*)(qsm + 2 * QTB);
    __nv_bfloat16* sKl = (__nv_bfloat16*)(qsm + 3 * QTB);
    float (*stage)[256] = (float(*)[256])qsm;          // overlay (post-mma)
    float* partial = (float*)(qsm + 49152);            // [4][128] overlay

    const int tid = threadIdx.x;
    const int w = tid >> 5;
    const int lid = tid & 31;
    const int wm = w & 1;
    const int wn = w >> 1;
    const int m0 = blockIdx.x * 128;
    const int n0 = blockIdx.y * 128;
    const int bh = blockIdx.z;

    const __nv_bfloat16* qb = g_qh + (size_t)bh * N_ * D_;
    const __nv_bfloat16* qlb = g_ql + (size_t)bh * N_ * D_;
    const __nv_bfloat16* kb = g_kh + (size_t)bh * N_ * D_;
    const __nv_bfloat16* klb = g_kl + (size_t)bh * N_ * D_;

#pragma unroll
    for (int it = 0; it < 3; it++) {
        const int v = tid + it * 256;
        const int row = v / 6;
        const int seg = (v % 6) * 8;
        const int qrow = min(n0 + row, N_ - 1);
        const int krow = min(m0 + row, N_ - 1);
        const int dst = row * QSTR + seg;
        *(uint4*)&sQh[dst] = *(const uint4*)(qb + (size_t)qrow * D_ + seg);
        *(uint4*)&sQl[dst] = *(const uint4*)(qlb + (size_t)qrow * D_ + seg);
        *(uint4*)&sKh[dst] = *(const uint4*)(kb + (size_t)krow * D_ + seg);
        *(uint4*)&sKl[dst] = *(const uint4*)(klb + (size_t)krow * D_ + seg);
    }
    __syncthreads();

    wmma::fragment<wmma::accumulator, 16, 16, 16, float> acc[4][2];
#pragma unroll
    for (int i = 0; i < 4; i++)
#pragma unroll
        for (int j = 0; j < 2; j++) wmma::fill_fragment(acc[i][j], 0.f);

#pragma unroll
    for (int ks = 0; ks < 3; ks++) {
        const int kk = ks * 16;
        wmma::fragment<wmma::matrix_a, 16, 16, 16, __nv_bfloat16, wmma::row_major> fah[4], fal[4];
        wmma::fragment<wmma::matrix_b, 16, 16, 16, __nv_bfloat16, wmma::col_major> fbh[2], fbl[2];
#pragma unroll
        for (int i = 0; i < 4; i++) {
            const int r = wm * 64 + i * 16;
            wmma::load_matrix_sync(fah[i], &sQh[r * QSTR + kk], QSTR);
            wmma::load_matrix_sync(fal[i], &sQl[r * QSTR + kk], QSTR);
        }
#pragma unroll
        for (int j = 0; j < 2; j++) {
            const int c = wn * 32 + j * 16;
            wmma::load_matrix_sync(fbh[j], &sKh[c * QSTR + kk], QSTR);
            wmma::load_matrix_sync(fbl[j], &sKl[c * QSTR + kk], QSTR);
        }
#pragma unroll
        for (int i = 0; i < 4; i++)
#pragma unroll
            for (int j = 0; j < 2; j++) {
                wmma::mma_sync(acc[i][j], fah[i], fbh[j], acc[i][j]);
                wmma::mma_sync(acc[i][j], fah[i], fbl[j], acc[i][j]);
                wmma::mma_sync(acc[i][j], fal[i], fbh[j], acc[i][j]);
            }
    }

    __syncthreads();   // smem tiles -> stage/partial overlay

    float* abase = attn + (size_t)bh * N_ * N_;
#pragma unroll
    for (int i = 0; i < 4; i++) {
        const int row0 = n0 + wm * 64 + i * 16;
        const bool rowok = (row0 < N_);
        float rs[8];
#pragma unroll
        for (int tt = 0; tt < 8; tt++) rs[tt] = 0.f;
#pragma unroll
        for (int j = 0; j < 2; j++) {
            const int col0 = m0 + wn * 32 + j * 16;
            const bool colok = (col0 < N_);
            __syncwarp();
            wmma::store_matrix_sync(&stage[w][0], acc[i][j], 16, wmma::mem_row_major);
            __syncwarp();
            if (colok) {
#pragma unroll
                for (int tt = 0; tt < 8; tt++) {
                    const int idx = tt * 32 + lid;
                    const float e = __expf(stage[w][idx]);
                    rs[tt] += e;
                    if (rowok) {
                        const int r = row0 + (idx >> 4);
                        const int c = col0 + (idx & 15);
                        abase[(size_t)r * N_ + c] = e;
                    }
                }
            }
        }
#pragma unroll
        for (int tt = 0; tt < 8; tt++) {
            float v = rs[tt];
            v += __shfl_xor_sync(0xffffffffu, v, 1);
            v += __shfl_xor_sync(0xffffffffu, v, 2);
            v += __shfl_xor_sync(0xffffffffu, v, 4);
            v += __shfl_xor_sync(0xffffffffu, v, 8);
            if ((lid & 15) == 0) {
                const int rl = wm * 64 + i * 16 + tt * 2 + (lid >> 4);
                partial[wn * 128 + rl] = v;
            }
        }
    }
    __syncthreads();
    if (tid < 128) {
        const int n = n0 + tid;
        if (n < N_) {
            g_psum[((size_t)bh * 7 + blockIdx.x) * N_ + n] =
                partial[tid] + partial[128 + tid] + partial[256 + tid] + partial[384 + tid];
        }
    }
}

// ======== fused: finalize attn ((1-g)E/S + g*pos) + AV + o-split ============
// grid (stripe 7, b 8, h 16) so blocks sharing pos[h] are adjacent (L2 reuse).
#define FAV_SMEM (2 * 112 * 120 * 2 + 448 + 7 * 256 * 4)   // 61376

__global__ void __launch_bounds__(256) fused_av(const float* __restrict__ gating,
                                                float* __restrict__ attn) {
    extern __shared__ char fsm[];
    __nv_bfloat16* sAh = (__nv_bfloat16*)fsm;                  // [112][120]
    __nv_bfloat16* sAl = (__nv_bfloat16*)(fsm + 26880);
    float* scoef = (float*)(fsm + 53760);                      // [112]
    float (*ostage)[256] = (float(*)[256])(fsm + 54208);       // [7][256]

    const int tid = threadIdx.x;
    const int w = tid >> 5;
    const int lid = tid & 31;
    const int b = blockIdx.y;
    const int h = blockIdx.z;
    const int bh = b * H_ + h;
    const int r0 = blockIdx.x * 112;

    const float g = 1.f / (1.f + __expf(-gating[h]));

    for (int row = tid; row < 112; row += 256) {
        float S = 0.f;
#pragma unroll
        for (int mb = 0; mb < 7; mb++)
            S += g_psum[((size_t)bh * 7 + mb) * N_ + r0 + row];
        scoef[row] = (1.f - g) / S;
    }
    __syncthreads();

    float* abase = attn + (size_t)bh * N_ * N_;
    const float* pbase = g_pos + (size_t)h * N_ * N_;
    const __nv_bfloat16* vhb = g_vh + (size_t)bh * N_ * D_;
    const __nv_bfloat16* vlb = g_vl + (size_t)bh * N_ * D_;

    wmma::fragment<wmma::accumulator, 16, 16, 16, float> acc[3];
#pragma unroll
    for (int j = 0; j < 3; j++) wmma::fill_fragment(acc[j], 0.f);

    for (int c = 0; c < 7; c++) {
        const int m0 = c * 112;
        for (int v = tid; v < 112 * 28; v += 256) {
            const int row = v / 28;
            const int cg = v - row * 28;
            const size_t gidx = (size_t)(r0 + row) * N_ + m0 + cg * 4;
            float4 E = *(const float4*)(abase + gidx);
            float4 p = *(const float4*)(pbase + gidx);
            const float cf = scoef[row];
            float4 a;
            a.x = cf * E.x + g * p.x;
            a.y = cf * E.y + g * p.y;
            a.z = cf * E.z + g * p.z;
            a.w = cf * E.w + g * p.w;
            *(float4*)(abase + gidx) = a;
            uint32_t h01 = pack_bf16x2(a.x, a.y);
            uint32_t h23 = pack_bf16x2(a.z, a.w);
            uint32_t l01 = pack_bf16x2(a.x - bfx2_lo(h01), a.y - bfx2_hi(h01));
            uint32_t l23 = pack_bf16x2(a.z - bfx2_lo(h23), a.w - bfx2_hi(h23));
            const int so = row * 120 + cg * 4;
            *(uint2*)&sAh[so] = make_uint2(h01, h23);
            *(uint2*)&sAl[so] = make_uint2(l01, l23);
        }
        __syncthreads();

        if (w < 7) {
#pragma unroll
            for (int kt = 0; kt < 7; kt++) {
                wmma::fragment<wmma::matrix_a, 16, 16, 16, __nv_bfloat16, wmma::row_major> fah, fal;
                wmma::load_matrix_sync(fah, &sAh[(w * 16) * 120 + kt * 16], 120);
                wmma::load_matrix_sync(fal, &sAl[(w * 16) * 120 + kt * 16], 120);
#pragma unroll
                for (int j = 0; j < 3; j++) {
                    wmma::fragment<wmma::matrix_b, 16, 16, 16, __nv_bfloat16, wmma::row_major> fbh, fbl;
                    wmma::load_matrix_sync(fbh, vhb + (size_t)(m0 + kt * 16) * D_ + j * 16, D_);
                    wmma::load_matrix_sync(fbl, vlb + (size_t)(m0 + kt * 16) * D_ + j * 16, D_);
                    wmma::mma_sync(acc[j], fah, fbh, acc[j]);
                    wmma::mma_sync(acc[j], fah, fbl, acc[j]);
                    wmma::mma_sync(acc[j], fal, fbh, acc[j]);
                }
            }
        }
        __syncthreads();
    }

    if (w < 7) {
#pragma unroll
        for (int j = 0; j < 3; j++) {
            __syncwarp();
            wmma::store_matrix_sync(&ostage[w][0], acc[j], 16, wmma::mem_row_major);
            __syncwarp();
#pragma unroll
            for (int tt = 0; tt < 8; tt++) {
                const int idx = tt * 32 + lid;
                const float v = ostage[w][idx];
                const int row = r0 + w * 16 + (idx >> 4);
                const int col = h * D_ + j * 16 + (idx & 15);
                const size_t dst = (size_t)(b * N_ + row) * C_ + col;
                __nv_bfloat16 hi = __float2bfloat16(v);
                g_oh[dst] = hi;
                g_ol[dst] = __float2bfloat16(v - __bfloat162float(hi));
            }
        }
    }
}

// ---------------- launch ----------------------------------------------------
extern "C" void kernel_launch(void* const* d_in, const int* in_sizes, int n_in,
                              void* d_out, int out_size) {
    const float* x      = (const float*)d_in[0];
    const float* Wq     = (const float*)d_in[1];
    const float* Wk     = (const float*)d_in[2];
    const float* Wv     = (const float*)d_in[3];
    const float* Wproj  = (const float*)d_in[4];
    const float* b_proj = (const float*)d_in[5];
    const float* W_pos  = (const float*)d_in[6];
    const float* b_pos  = (const float*)d_in[7];
    const float* gating = (const float*)d_in[8];

    float* out_o    = (float*)d_out;                              // [B,N,C]
    float* out_attn = out_o + (size_t)B_ * N_ * C_;               // [B,H,N,N]
    float* out_v    = out_attn + (size_t)B_ * H_ * N_ * N_;       // [B,H,N,D]

    cudaFuncSetAttribute((const void*)tc_gemm,
                         cudaFuncAttributeMaxDynamicSharedMemorySize, TC_SMEM);
    cudaFuncSetAttribute((const void*)qk_gemm,
                         cudaFuncAttributeMaxDynamicSharedMemorySize, QK_SMEM);
    cudaFuncSetAttribute((const void*)fused_av,
                         cudaFuncAttributeMaxDynamicSharedMemorySize, FAV_SMEM);

    split_x<<<(M_ * C_ / 4 + 255) / 256, 256>>>(x);                            // 0
    split_w<<<dim3((C_ * C_ / 4 + 255) / 256, 4), 256>>>(Wq, Wk, Wv, Wproj);   // 1
    pos_kernel<<<dim3(98, H_), 256>>>(W_pos, b_pos);                           // 2
    tc_gemm<<<dim3(C_ / 128, M_ / 128, 3), 256, TC_SMEM>>>(0, nullptr, out_v, nullptr); // 3 <- profiled
    qk_gemm<<<dim3(7, 7, BH_), 256, QK_SMEM>>>(out_attn);                      // 4
    fused_av<<<dim3(7, B_, H_), 256, FAV_SMEM>>>(gating, out_attn);            // 5
    tc_gemm<<<dim3(C_ / 128, M_ / 128, 1), 256, TC_SMEM>>>(1, out_o, nullptr, b_proj);  // 6
}

// round 13
// speedup vs baseline: 1.6391x; 1.6391x over previous
#include <cuda_runtime.h>
#include <cuda_bf16.h>
#include <mma.h>
#include <cstddef>
#include <cstdint>

using namespace nvcuda;

// Problem constants
#define B_ 8
#define N_ 784
#define C_ 768
#define H_ 16
#define D_ 48
#define S_ 28
#define M_ (B_ * N_)          // 6272 rows
#define BH_ (B_ * H_)         // 128
#define SCALE_ 0.14433756729740643f  // 48^-0.5

__device__ __forceinline__ uint32_t smem_u32(const void* p) {
    uint32_t a;
    asm("{ .reg .u64 t; cvta.to.shared.u64 t, %1; cvt.u32.u64 %0, t; }" : "=r"(a) : "l"(p));
    return a;
}
#define CP16(dst, src) \
    asm volatile("cp.async.ca.shared.global [%0], [%1], 16;" :: "r"(dst), "l"(src))
#define CP_COMMIT() asm volatile("cp.async.commit_group;")
#define CP_WAIT1()  asm volatile("cp.async.wait_group 1;")
#define CP_WAIT0()  asm volatile("cp.async.wait_group 0;")

__device__ __forceinline__ uint32_t pack_bf16x2(float lo, float hi) {
    uint32_t r;
    asm("cvt.rn.bf16x2.f32 %0, %1, %2;" : "=r"(r) : "f"(hi), "f"(lo));
    return r;
}
__device__ __forceinline__ float bfx2_lo(uint32_t pk) { return __uint_as_float(pk << 16); }
__device__ __forceinline__ float bfx2_hi(uint32_t pk) { return __uint_as_float(pk & 0xFFFF0000u); }

// ---------------- scratch (device globals; no allocation allowed) ----------
__device__ float g_pos[(size_t)H_ * N_ * N_];  // softmaxed positional scores
__device__ float g_psum[(size_t)BH_ * 7 * N_]; // per-colblock exp row sums
__device__ __align__(16) __nv_bfloat16 g_xh[(size_t)M_ * C_], g_xl[(size_t)M_ * C_];
__device__ __align__(16) __nv_bfloat16 g_wh[4 * (size_t)C_ * C_], g_wl[4 * (size_t)C_ * C_];
__device__ __align__(16) __nv_bfloat16 g_oh[(size_t)M_ * C_], g_ol[(size_t)M_ * C_];
// per-head split operands: [bh][n][48]
__device__ __align__(16) __nv_bfloat16 g_qh[(size_t)BH_ * N_ * D_], g_ql[(size_t)BH_ * N_ * D_];
__device__ __align__(16) __nv_bfloat16 g_kh[(size_t)BH_ * N_ * D_], g_kl[(size_t)BH_ * N_ * D_];
__device__ __align__(16) __nv_bfloat16 g_vh[(size_t)BH_ * N_ * D_], g_vl[(size_t)BH_ * N_ * D_];

// ---------------- fp32 -> (hi, lo) bf16 split kernels -----------------------
__device__ __forceinline__ void split4(const float* src, __nv_bfloat16* hi,
                                       __nv_bfloat16* lo, size_t i4) {
    float4 v = *(const float4*)(src + i4 * 4);
    uint32_t h01 = pack_bf16x2(v.x, v.y);
    uint32_t h23 = pack_bf16x2(v.z, v.w);
    uint32_t l01 = pack_bf16x2(v.x - bfx2_lo(h01), v.y - bfx2_hi(h01));
    uint32_t l23 = pack_bf16x2(v.z - bfx2_lo(h23), v.w - bfx2_hi(h23));
    *(uint2*)(hi + i4 * 4) = make_uint2(h01, h23);
    *(uint2*)(lo + i4 * 4) = make_uint2(l01, l23);
}

__global__ void __launch_bounds__(256) split_x(const float* __restrict__ x) {
    size_t i = (size_t)blockIdx.x * 256 + threadIdx.x;
    if (i < (size_t)M_ * C_ / 4) split4(x, g_xh, g_xl, i);
}
__global__ void __launch_bounds__(256) split_w(const float* __restrict__ Wq,
                                               const float* __restrict__ Wk,
                                               const float* __restrict__ Wv,
                                               const float* __restrict__ Wp) {
    const int z = blockIdx.y;
    const float* src = (z == 0) ? Wq : (z == 1) ? Wk : (z == 2) ? Wv : Wp;
    size_t i = (size_t)blockIdx.x * 256 + threadIdx.x;
    if (i < (size_t)C_ * C_ / 4)
        split4(src, g_wh + (size_t)z * C_ * C_, g_wl + (size_t)z * C_ * C_, i);
}

// ---------------- positional scores: warp-per-row softmax -------------------
__global__ void __launch_bounds__(256) pos_kernel(const float* __restrict__ W_pos,
                                                  const float* __restrict__ b_pos) {
    const int h = blockIdx.y;
    const int n = blockIdx.x * 8 + (threadIdx.x >> 5);
    const int lid = threadIdx.x & 31;
    const float w0 = W_pos[h * 3 + 0];
    const float w1 = W_pos[h * 3 + 1];
    const float w2 = W_pos[h * 3 + 2];
    const float bp = b_pos[h];
    const int i1 = n / S_;
    const int j1 = n % S_;

    float buf[25];
    float mx = -1e30f;
    int m = lid;
    int mi = lid / S_, mj = lid % S_;
#pragma unroll
    for (int t = 0; t < 25; t++) {
        if (m < N_) {
            const float dx = (float)(mj - j1);
            const float dy = (float)(mi - i1);
            const float l = w0 * dx + w1 * dy + w2 * (dx * dx + dy * dy) + bp;
            buf[t] = l;
            mx = fmaxf(mx, l);
        } else buf[t] = -1e30f;
        m += 32;
        mi += 1; mj += 4;
        if (mj >= S_) { mj -= S_; mi += 1; }
    }
#pragma unroll
    for (int off = 16; off > 0; off >>= 1)
        mx = fmaxf(mx, __shfl_xor_sync(0xffffffffu, mx, off));

    float sum = 0.f;
#pragma unroll
    for (int t = 0; t < 25; t++) {
        const float e = __expf(buf[t] - mx);
        buf[t] = e;
        sum += e;
    }
#pragma unroll
    for (int off = 16; off > 0; off >>= 1)
        sum += __shfl_xor_sync(0xffffffffu, sum, off);
    const float inv = 1.f / sum;

    float* row = g_pos + ((size_t)h * N_ + n) * N_;
    m = lid;
#pragma unroll
    for (int t = 0; t < 25; t++) {
        if (m < N_) row[m] = buf[t] * inv;
        m += 32;
    }
}

// ================= wmma split-bf16 GEMM, cp.async double buffered ===========
// C[i,j] = sum_k A[i,k]*B[j,k]  via  Ah*Bh + Ah*Bl + Al*Bh  (fp32 accum)
// __launch_bounds__(256,2): cap 128 regs -> 2 CTAs/SM (16 warps)
#define TSTR 40                   // smem tile stride (bf16 elems)
#define TCB 40960                 // bytes per stage (4 arrays x 10240)
#define TC_SMEM (2 * TCB)         // stage floats overlay pipeline buffer 0

__global__ void __launch_bounds__(256, 2) tc_gemm(int mode, float* __restrict__ outC,
                                                  float* __restrict__ out_v,
                                                  const float* __restrict__ bias) {
    extern __shared__ char gsm[];
    float (*stage)[256] = (float(*)[256])gsm;   // valid AFTER the k-loop only
    const uint32_t sb = smem_u32(gsm);

    const int tid = threadIdx.x;
    const int w = tid >> 5;
    const int lid = tid & 31;
    const int wm = w & 1;          // 0..1  (64 rows each)
    const int wn = w >> 1;         // 0..3  (32 cols each)
    const int j0 = blockIdx.x * 128;
    const int i0 = blockIdx.y * 128;
    const int z = blockIdx.z;

    const __nv_bfloat16 *Ah, *Al, *Bh, *Bl;
    if (mode == 0) {
        Ah = g_xh; Al = g_xl;
        Bh = g_wh + (size_t)z * C_ * C_; Bl = g_wl + (size_t)z * C_ * C_;
    } else {
        Ah = g_oh; Al = g_ol;
        Bh = g_wh + (size_t)3 * C_ * C_; Bl = g_wl + (size_t)3 * C_ * C_;
    }

    const int prow = tid >> 2;            // 0..63
    const int pseg = (tid & 3) * 8;       // bf16 offset within 32

    wmma::fragment<wmma::accumulator, 16, 16, 16, float> acc[4][2];
#pragma unroll
    for (int i = 0; i < 4; i++)
#pragma unroll
        for (int j = 0; j < 2; j++) wmma::fill_fragment(acc[i][j], 0.f);

    auto issue = [&](int ch, int s) {
        const int koff = ch * 32 + pseg;
#pragma unroll
        for (int it = 0; it < 2; it++) {
            const int row = prow + it * 64;
            const uint32_t d = sb + s * TCB + (row * TSTR + pseg) * 2;
            CP16(d +     0, Ah + (size_t)(i0 + row) * C_ + koff);
            CP16(d + 10240, Al + (size_t)(i0 + row) * C_ + koff);
            CP16(d + 20480, Bh + (size_t)(j0 + row) * C_ + koff);
            CP16(d + 30720, Bl + (size_t)(j0 + row) * C_ + koff);
        }
        CP_COMMIT();
    };

    issue(0, 0);
    for (int ch = 0; ch < C_ / 32; ch++) {
        const int s = ch & 1;
        if (ch + 1 < C_ / 32) { issue(ch + 1, (ch + 1) & 1); CP_WAIT1(); }
        else                  { CP_WAIT0(); }
        __syncthreads();

        const __nv_bfloat16* bAh = (const __nv_bfloat16*)(gsm + s * TCB);
        const __nv_bfloat16* bAl = (const __nv_bfloat16*)(gsm + s * TCB + 10240);
        const __nv_bfloat16* bBh = (const __nv_bfloat16*)(gsm + s * TCB + 20480);
        const __nv_bfloat16* bBl = (const __nv_bfloat16*)(gsm + s * TCB + 30720);

        // low-register order: B-pair resident, stream A fragments one at a time
#pragma unroll
        for (int ks = 0; ks < 2; ks++) {
            const int kk = ks * 16;
#pragma unroll
            for (int j = 0; j < 2; j++) {
                const int c = wn * 32 + j * 16;
                wmma::fragment<wmma::matrix_b, 16, 16, 16, __nv_bfloat16, wmma::col_major> fbh, fbl;
                wmma::load_matrix_sync(fbh, &bBh[c * TSTR + kk], TSTR);
                wmma::load_matrix_sync(fbl, &bBl[c * TSTR + kk], TSTR);
#pragma unroll
                for (int i = 0; i < 4; i++) {
                    const int r = wm * 64 + i * 16;
                    wmma::fragment<wmma::matrix_a, 16, 16, 16, __nv_bfloat16, wmma::row_major> fa;
                    wmma::load_matrix_sync(fa, &bAh[r * TSTR + kk], TSTR);
                    wmma::mma_sync(acc[i][j], fa, fbh, acc[i][j]);
                    wmma::mma_sync(acc[i][j], fa, fbl, acc[i][j]);
                    wmma::load_matrix_sync(fa, &bAl[r * TSTR + kk], TSTR);
                    wmma::mma_sync(acc[i][j], fa, fbh, acc[i][j]);
                }
            }
        }
        __syncthreads();
    }

    if (mode == 1) {
#pragma unroll
        for (int i = 0; i < 4; i++) {
            const int row0 = i0 + wm * 64 + i * 16;
#pragma unroll
            for (int j = 0; j < 2; j++) {
                const int col0 = j0 + wn * 32 + j * 16;
                __syncwarp();
                wmma::store_matrix_sync(&stage[w][0], acc[i][j], 16, wmma::mem_row_major);
                __syncwarp();
#pragma unroll
                for (int tt = 0; tt < 8; tt++) {
                    const int idx = tt * 32 + lid;
                    const int r = idx >> 4;
                    const int c = idx & 15;
                    outC[(size_t)(row0 + r) * C_ + col0 + c] = stage[w][idx] + bias[col0 + c];
                }
            }
        }
        return;
    }

    // mode 0 epilogue: stage fragments, vectorized scatter to per-head splits
#pragma unroll
    for (int i = 0; i < 4; i++) {
        const int row0 = i0 + wm * 64 + i * 16;
#pragma unroll
        for (int j = 0; j < 2; j++) {
            const int col0 = j0 + wn * 32 + j * 16;
            __syncwarp();
            wmma::store_matrix_sync(&stage[w][0], acc[i][j], 16, wmma::mem_row_major);
            __syncwarp();
#pragma unroll
            for (int half = 0; half < 2; half++) {
                const int r = half * 8 + (lid >> 2);
                const int c4 = (lid & 3) * 4;
                float4 v4 = *(float4*)&stage[w][r * 16 + c4];
                const int grow = row0 + r;
                const int gcol = col0 + c4;                  // 4-col group, never crosses head
                const int b = grow / N_;
                const int n = grow % N_;
                const int h = gcol / D_;
                const int d = gcol % D_;
                const size_t dst = ((size_t)(b * H_ + h) * N_ + n) * D_ + d;
                if (z == 0) {
                    v4.x *= SCALE_; v4.y *= SCALE_; v4.z *= SCALE_; v4.w *= SCALE_;
                }
                const uint32_t h01 = pack_bf16x2(v4.x, v4.y);
                const uint32_t h23 = pack_bf16x2(v4.z, v4.w);
                const uint32_t l01 = pack_bf16x2(v4.x - bfx2_lo(h01), v4.y - bfx2_hi(h01));
                const uint32_t l23 = pack_bf16x2(v4.z - bfx2_lo(h23), v4.w - bfx2_hi(h23));
                __nv_bfloat16 *ph, *pl;
                if (z == 0)      { ph = g_qh; pl = g_ql; }
                else if (z == 1) { ph = g_kh; pl = g_kl; }
                else             { ph = g_vh; pl = g_vl; *(float4*)(out_v + dst) = v4; }
                *(uint2*)(ph + dst) = make_uint2(h01, h23);
                *(uint2*)(pl + dst) = make_uint2(l01, l23);
            }
        }
    }
}

// ================ QK^T wmma GEMM -> E = exp(score) + partial row sums =======
// QSTR=56: 112B row stride -> 16B-aligned uint4 stores AND conflict-free LDSM
#define QSTR 56
#define QTB (128 * QSTR * 2)            // 14336 bytes per tile
#define QK_SMEM (4 * QTB)               // 57344

__global__ void __launch_bounds__(256, 2) qk_gemm(float* __restrict__ attn) {
    extern __shared__ char qsm[];
    __nv_bfloat16* sQh = (__nv_bfloat16*)qsm;
    __nv_bfloat16* sQl = (__nv_bfloat16*)(qsm + QTB);
    __nv_bfloat16* sKh = (__nv_bfloat16*)(qsm + 2 * QTB);
    __nv_bfloat16* sKl = (__nv_bfloat16*)(qsm + 3 * QTB);
    float (*stage)[256] = (float(*)[256])qsm;          // overlay (post-mma)
    float* partial = (float*)(qsm + 49152);            // [4][128] overlay

    const int tid = threadIdx.x;
    const int w = tid >> 5;
    const int lid = tid & 31;
    const int wm = w & 1;
    const int wn = w >> 1;
    const int m0 = blockIdx.x * 128;
    const int n0 = blockIdx.y * 128;
    const int bh = blockIdx.z;

    const __nv_bfloat16* qb = g_qh + (size_t)bh * N_ * D_;
    const __nv_bfloat16* qlb = g_ql + (size_t)bh * N_ * D_;
    const __nv_bfloat16* kb = g_kh + (size_t)bh * N_ * D_;
    const __nv_bfloat16* klb = g_kl + (size_t)bh * N_ * D_;

#pragma unroll
    for (int it = 0; it < 3; it++) {
        const int v = tid + it * 256;
        const int row = v / 6;
        const int seg = (v % 6) * 8;
        const int qrow = min(n0 + row, N_ - 1);
        const int krow = min(m0 + row, N_ - 1);
        const int dst = row * QSTR + seg;
        *(uint4*)&sQh[dst] = *(const uint4*)(qb + (size_t)qrow * D_ + seg);
        *(uint4*)&sQl[dst] = *(const uint4*)(qlb + (size_t)qrow * D_ + seg);
        *(uint4*)&sKh[dst] = *(const uint4*)(kb + (size_t)krow * D_ + seg);
        *(uint4*)&sKl[dst] = *(const uint4*)(klb + (size_t)krow * D_ + seg);
    }
    __syncthreads();

    wmma::fragment<wmma::accumulator, 16, 16, 16, float> acc[4][2];
#pragma unroll
    for (int i = 0; i < 4; i++)
#pragma unroll
        for (int j = 0; j < 2; j++) wmma::fill_fragment(acc[i][j], 0.f);

#pragma unroll
    for (int ks = 0; ks < 3; ks++) {
        const int kk = ks * 16;
#pragma unroll
        for (int j = 0; j < 2; j++) {
            const int c = wn * 32 + j * 16;
            wmma::fragment<wmma::matrix_b, 16, 16, 16, __nv_bfloat16, wmma::col_major> fbh, fbl;
            wmma::load_matrix_sync(fbh, &sKh[c * QSTR + kk], QSTR);
            wmma::load_matrix_sync(fbl, &sKl[c * QSTR + kk], QSTR);
#pragma unroll
            for (int i = 0; i < 4; i++) {
                const int r = wm * 64 + i * 16;
                wmma::fragment<wmma::matrix_a, 16, 16, 16, __nv_bfloat16, wmma::row_major> fa;
                wmma::load_matrix_sync(fa, &sQh[r * QSTR + kk], QSTR);
                wmma::mma_sync(acc[i][j], fa, fbh, acc[i][j]);
                wmma::mma_sync(acc[i][j], fa, fbl, acc[i][j]);
                wmma::load_matrix_sync(fa, &sQl[r * QSTR + kk], QSTR);
                wmma::mma_sync(acc[i][j], fa, fbh, acc[i][j]);
            }
        }
    }

    __syncthreads();   // smem tiles -> stage/partial overlay

    float* abase = attn + (size_t)bh * N_ * N_;
#pragma unroll
    for (int i = 0; i < 4; i++) {
        const int row0 = n0 + wm * 64 + i * 16;
        const bool rowok = (row0 < N_);
        float rs[8];
#pragma unroll
        for (int tt = 0; tt < 8; tt++) rs[tt] = 0.f;
#pragma unroll
        for (int j = 0; j < 2; j++) {
            const int col0 = m0 + wn * 32 + j * 16;
            const bool colok = (col0 < N_);
            __syncwarp();
            wmma::store_matrix_sync(&stage[w][0], acc[i][j], 16, wmma::mem_row_major);
            __syncwarp();
            if (colok) {
#pragma unroll
                for (int tt = 0; tt < 8; tt++) {
                    const int idx = tt * 32 + lid;
                    const float e = __expf(stage[w][idx]);
                    rs[tt] += e;
                    if (rowok) {
                        const int r = row0 + (idx >> 4);
                        const int c = col0 + (idx & 15);
                        abase[(size_t)r * N_ + c] = e;
                    }
                }
            }
        }
#pragma unroll
        for (int tt = 0; tt < 8; tt++) {
            float v = rs[tt];
            v += __shfl_xor_sync(0xffffffffu, v, 1);
            v += __shfl_xor_sync(0xffffffffu, v, 2);
            v += __shfl_xor_sync(0xffffffffu, v, 4);
            v += __shfl_xor_sync(0xffffffffu, v, 8);
            if ((lid & 15) == 0) {
                const int rl = wm * 64 + i * 16 + tt * 2 + (lid >> 4);
                partial[wn * 128 + rl] = v;
            }
        }
    }
    __syncthreads();
    if (tid < 128) {
        const int n = n0 + tid;
        if (n < N_) {
            g_psum[((size_t)bh * 7 + blockIdx.x) * N_ + n] =
                partial[tid] + partial[128 + tid] + partial[256 + tid] + partial[384 + tid];
        }
    }
}

// ======== fused: finalize attn ((1-g)E/S + g*pos) + AV + o-split ============
// grid (stripe 7, b 8, h 16) so blocks sharing pos[h] are adjacent (L2 reuse).
#define FAV_SMEM (2 * 112 * 120 * 2 + 448 + 7 * 256 * 4)   // 61376

__global__ void __launch_bounds__(256) fused_av(const float* __restrict__ gating,
                                                float* __restrict__ attn) {
    extern __shared__ char fsm[];
    __nv_bfloat16* sAh = (__nv_bfloat16*)fsm;                  // [112][120]
    __nv_bfloat16* sAl = (__nv_bfloat16*)(fsm + 26880);
    float* scoef = (float*)(fsm + 53760);                      // [112]
    float (*ostage)[256] = (float(*)[256])(fsm + 54208);       // [7][256]

    const int tid = threadIdx.x;
    const int w = tid >> 5;
    const int lid = tid & 31;
    const int b = blockIdx.y;
    const int h = blockIdx.z;
    const int bh = b * H_ + h;
    const int r0 = blockIdx.x * 112;

    const float g = 1.f / (1.f + __expf(-gating[h]));

    for (int row = tid; row < 112; row += 256) {
        float S = 0.f;
#pragma unroll
        for (int mb = 0; mb < 7; mb++)
            S += g_psum[((size_t)bh * 7 + mb) * N_ + r0 + row];
        scoef[row] = (1.f - g) / S;
    }
    __syncthreads();

    float* abase = attn + (size_t)bh * N_ * N_;
    const float* pbase = g_pos + (size_t)h * N_ * N_;
    const __nv_bfloat16* vhb = g_vh + (size_t)bh * N_ * D_;
    const __nv_bfloat16* vlb = g_vl + (size_t)bh * N_ * D_;

    wmma::fragment<wmma::accumulator, 16, 16, 16, float> acc[3];
#pragma unroll
    for (int j = 0; j < 3; j++) wmma::fill_fragment(acc[j], 0.f);

    for (int c = 0; c < 7; c++) {
        const int m0 = c * 112;
        for (int v = tid; v < 112 * 28; v += 256) {
            const int row = v / 28;
            const int cg = v - row * 28;
            const size_t gidx = (size_t)(r0 + row) * N_ + m0 + cg * 4;
            float4 E = *(const float4*)(abase + gidx);
            float4 p = *(const float4*)(pbase + gidx);
            const float cf = scoef[row];
            float4 a;
            a.x = cf * E.x + g * p.x;
            a.y = cf * E.y + g * p.y;
            a.z = cf * E.z + g * p.z;
            a.w = cf * E.w + g * p.w;
            *(float4*)(abase + gidx) = a;
            uint32_t h01 = pack_bf16x2(a.x, a.y);
            uint32_t h23 = pack_bf16x2(a.z, a.w);
            uint32_t l01 = pack_bf16x2(a.x - bfx2_lo(h01), a.y - bfx2_hi(h01));
            uint32_t l23 = pack_bf16x2(a.z - bfx2_lo(h23), a.w - bfx2_hi(h23));
            const int so = row * 120 + cg * 4;
            *(uint2*)&sAh[so] = make_uint2(h01, h23);
            *(uint2*)&sAl[so] = make_uint2(l01, l23);
        }
        __syncthreads();

        if (w < 7) {
#pragma unroll
            for (int kt = 0; kt < 7; kt++) {
                wmma::fragment<wmma::matrix_a, 16, 16, 16, __nv_bfloat16, wmma::row_major> fah, fal;
                wmma::load_matrix_sync(fah, &sAh[(w * 16) * 120 + kt * 16], 120);
                wmma::load_matrix_sync(fal, &sAl[(w * 16) * 120 + kt * 16], 120);
#pragma unroll
                for (int j = 0; j < 3; j++) {
                    wmma::fragment<wmma::matrix_b, 16, 16, 16, __nv_bfloat16, wmma::row_major> fbh, fbl;
                    wmma::load_matrix_sync(fbh, vhb + (size_t)(m0 + kt * 16) * D_ + j * 16, D_);
                    wmma::load_matrix_sync(fbl, vlb + (size_t)(m0 + kt * 16) * D_ + j * 16, D_);
                    wmma::mma_sync(acc[j], fah, fbh, acc[j]);
                    wmma::mma_sync(acc[j], fah, fbl, acc[j]);
                    wmma::mma_sync(acc[j], fal, fbh, acc[j]);
                }
            }
        }
        __syncthreads();
    }

    if (w < 7) {
#pragma unroll
        for (int j = 0; j < 3; j++) {
            __syncwarp();
            wmma::store_matrix_sync(&ostage[w][0], acc[j], 16, wmma::mem_row_major);
            __syncwarp();
#pragma unroll
            for (int tt = 0; tt < 8; tt++) {
                const int idx = tt * 32 + lid;
                const float v = ostage[w][idx];
                const int row = r0 + w * 16 + (idx >> 4);
                const int col = h * D_ + j * 16 + (idx & 15);
                const size_t dst = (size_t)(b * N_ + row) * C_ + col;
                __nv_bfloat16 hi = __float2bfloat16(v);
                g_oh[dst] = hi;
                g_ol[dst] = __float2bfloat16(v - __bfloat162float(hi));
            }
        }
    }
}

// ---------------- launch ----------------------------------------------------
extern "C" void kernel_launch(void* const* d_in, const int* in_sizes, int n_in,
                              void* d_out, int out_size) {
    const float* x      = (const float*)d_in[0];
    const float* Wq     = (const float*)d_in[1];
    const float* Wk     = (const float*)d_in[2];
    const float* Wv     = (const float*)d_in[3];
    const float* Wproj  = (const float*)d_in[4];
    const float* b_proj = (const float*)d_in[5];
    const float* W_pos  = (const float*)d_in[6];
    const float* b_pos  = (const float*)d_in[7];
    const float* gating = (const float*)d_in[8];

    float* out_o    = (float*)d_out;                              // [B,N,C]
    float* out_attn = out_o + (size_t)B_ * N_ * C_;               // [B,H,N,N]
    float* out_v    = out_attn + (size_t)B_ * H_ * N_ * N_;       // [B,H,N,D]

    cudaFuncSetAttribute((const void*)tc_gemm,
                         cudaFuncAttributeMaxDynamicSharedMemorySize, TC_SMEM);
    cudaFuncSetAttribute((const void*)qk_gemm,
                         cudaFuncAttributeMaxDynamicSharedMemorySize, QK_SMEM);
    cudaFuncSetAttribute((const void*)fused_av,
                         cudaFuncAttributeMaxDynamicSharedMemorySize, FAV_SMEM);

    split_x<<<(M_ * C_ / 4 + 255) / 256, 256>>>(x);                            // 0
    split_w<<<dim3((C_ * C_ / 4 + 255) / 256, 4), 256>>>(Wq, Wk, Wv, Wproj);   // 1
    pos_kernel<<<dim3(98, H_), 256>>>(W_pos, b_pos);                           // 2
    tc_gemm<<<dim3(C_ / 128, M_ / 128, 3), 256, TC_SMEM>>>(0, nullptr, out_v, nullptr); // 3 <- profiled
    qk_gemm<<<dim3(7, 7, BH_), 256, QK_SMEM>>>(out_attn);                      // 4
    fused_av<<<dim3(7, B_, H_), 256, FAV_SMEM>>>(gating, out_attn);            // 5
    tc_gemm<<<dim3(C_ / 128, M_ / 128, 1), 256, TC_SMEM>>>(1, out_o, nullptr, b_proj);  // 6
}

// round 14
// speedup vs baseline: 1.7082x; 1.0422x over previous
#include <cuda_runtime.h>
#include <cuda_bf16.h>
#include <mma.h>
#include <cstddef>
#include <cstdint>

using namespace nvcuda;

// Problem constants
#define B_ 8
#define N_ 784
#define C_ 768
#define H_ 16
#define D_ 48
#define S_ 28
#define M_ (B_ * N_)          // 6272 rows
#define BH_ (B_ * H_)         // 128
#define SCALE_ 0.14433756729740643f  // 48^-0.5

__device__ __forceinline__ uint32_t smem_u32(const void* p) {
    uint32_t a;
    asm("{ .reg .u64 t; cvta.to.shared.u64 t, %1; cvt.u32.u64 %0, t; }" : "=r"(a) : "l"(p));
    return a;
}
#define CP16(dst, src) \
    asm volatile("cp.async.ca.shared.global [%0], [%1], 16;" :: "r"(dst), "l"(src))
#define CP_COMMIT() asm volatile("cp.async.commit_group;")
#define CP_WAIT1()  asm volatile("cp.async.wait_group 1;")
#define CP_WAIT0()  asm volatile("cp.async.wait_group 0;")

__device__ __forceinline__ uint32_t pack_bf16x2(float lo, float hi) {
    uint32_t r;
    asm("cvt.rn.bf16x2.f32 %0, %1, %2;" : "=r"(r) : "f"(hi), "f"(lo));
    return r;
}
__device__ __forceinline__ float bfx2_lo(uint32_t pk) { return __uint_as_float(pk << 16); }
__device__ __forceinline__ float bfx2_hi(uint32_t pk) { return __uint_as_float(pk & 0xFFFF0000u); }

// ---------------- scratch (device globals; no allocation allowed) ----------
__device__ float g_pos[(size_t)H_ * N_ * N_];  // softmaxed positional scores
__device__ float g_psum[(size_t)BH_ * 7 * N_]; // per-colblock exp row sums
__device__ __align__(16) __nv_bfloat16 g_xh[(size_t)M_ * C_], g_xl[(size_t)M_ * C_];
__device__ __align__(16) __nv_bfloat16 g_wh[4 * (size_t)C_ * C_], g_wl[4 * (size_t)C_ * C_];
__device__ __align__(16) __nv_bfloat16 g_oh[(size_t)M_ * C_], g_ol[(size_t)M_ * C_];
// per-head split operands: [bh][n][48]
__device__ __align__(16) __nv_bfloat16 g_qh[(size_t)BH_ * N_ * D_], g_ql[(size_t)BH_ * N_ * D_];
__device__ __align__(16) __nv_bfloat16 g_kh[(size_t)BH_ * N_ * D_], g_kl[(size_t)BH_ * N_ * D_];
__device__ __align__(16) __nv_bfloat16 g_vh[(size_t)BH_ * N_ * D_], g_vl[(size_t)BH_ * N_ * D_];

// ---------------- fp32 -> (hi, lo) bf16 split kernels -----------------------
__device__ __forceinline__ void split4(const float* src, __nv_bfloat16* hi,
                                       __nv_bfloat16* lo, size_t i4) {
    float4 v = *(const float4*)(src + i4 * 4);
    uint32_t h01 = pack_bf16x2(v.x, v.y);
    uint32_t h23 = pack_bf16x2(v.z, v.w);
    uint32_t l01 = pack_bf16x2(v.x - bfx2_lo(h01), v.y - bfx2_hi(h01));
    uint32_t l23 = pack_bf16x2(v.z - bfx2_lo(h23), v.w - bfx2_hi(h23));
    *(uint2*)(hi + i4 * 4) = make_uint2(h01, h23);
    *(uint2*)(lo + i4 * 4) = make_uint2(l01, l23);
}

__global__ void __launch_bounds__(256) split_x(const float* __restrict__ x) {
    size_t i = (size_t)blockIdx.x * 256 + threadIdx.x;
    if (i < (size_t)M_ * C_ / 4) split4(x, g_xh, g_xl, i);
}
__global__ void __launch_bounds__(256) split_w(const float* __restrict__ Wq,
                                               const float* __restrict__ Wk,
                                               const float* __restrict__ Wv,
                                               const float* __restrict__ Wp) {
    const int z = blockIdx.y;
    const float* src = (z == 0) ? Wq : (z == 1) ? Wk : (z == 2) ? Wv : Wp;
    size_t i = (size_t)blockIdx.x * 256 + threadIdx.x;
    if (i < (size_t)C_ * C_ / 4)
        split4(src, g_wh + (size_t)z * C_ * C_, g_wl + (size_t)z * C_ * C_, i);
}

// ---------------- positional scores: warp-per-row softmax -------------------
__global__ void __launch_bounds__(256) pos_kernel(const float* __restrict__ W_pos,
                                                  const float* __restrict__ b_pos) {
    const int h = blockIdx.y;
    const int n = blockIdx.x * 8 + (threadIdx.x >> 5);
    const int lid = threadIdx.x & 31;
    const float w0 = W_pos[h * 3 + 0];
    const float w1 = W_pos[h * 3 + 1];
    const float w2 = W_pos[h * 3 + 2];
    const float bp = b_pos[h];
    const int i1 = n / S_;
    const int j1 = n % S_;

    float buf[25];
    float mx = -1e30f;
    int m = lid;
    int mi = lid / S_, mj = lid % S_;
#pragma unroll
    for (int t = 0; t < 25; t++) {
        if (m < N_) {
            const float dx = (float)(mj - j1);
            const float dy = (float)(mi - i1);
            const float l = w0 * dx + w1 * dy + w2 * (dx * dx + dy * dy) + bp;
            buf[t] = l;
            mx = fmaxf(mx, l);
        } else buf[t] = -1e30f;
        m += 32;
        mi += 1; mj += 4;
        if (mj >= S_) { mj -= S_; mi += 1; }
    }
#pragma unroll
    for (int off = 16; off > 0; off >>= 1)
        mx = fmaxf(mx, __shfl_xor_sync(0xffffffffu, mx, off));

    float sum = 0.f;
#pragma unroll
    for (int t = 0; t < 25; t++) {
        const float e = __expf(buf[t] - mx);
        buf[t] = e;
        sum += e;
    }
#pragma unroll
    for (int off = 16; off > 0; off >>= 1)
        sum += __shfl_xor_sync(0xffffffffu, sum, off);
    const float inv = 1.f / sum;

    float* row = g_pos + ((size_t)h * N_ + n) * N_;
    m = lid;
#pragma unroll
    for (int t = 0; t < 25; t++) {
        if (m < N_) row[m] = buf[t] * inv;
        m += 32;
    }
}

// ================= wmma split-bf16 GEMM, cp.async double buffered ===========
// C[i,j] = sum_k A[i,k]*B[j,k]  via  Ah*Bh + Ah*Bl + Al*Bh  (fp32 accum)
// __launch_bounds__(256,2): cap 128 regs -> 2 CTAs/SM (16 warps)
#define TSTR 40                   // smem tile stride (bf16 elems)
#define TCB 40960                 // bytes per stage (4 arrays x 10240)
#define TC_SMEM (2 * TCB)         // stage floats overlay pipeline buffer 0

__global__ void __launch_bounds__(256, 2) tc_gemm(int mode, float* __restrict__ outC,
                                                  float* __restrict__ out_v,
                                                  const float* __restrict__ bias) {
    extern __shared__ char gsm[];
    float (*stage)[256] = (float(*)[256])gsm;   // valid AFTER the k-loop only
    const uint32_t sb = smem_u32(gsm);

    const int tid = threadIdx.x;
    const int w = tid >> 5;
    const int lid = tid & 31;
    const int wm = w & 1;          // 0..1  (64 rows each)
    const int wn = w >> 1;         // 0..3  (32 cols each)
    const int j0 = blockIdx.x * 128;
    const int i0 = blockIdx.y * 128;
    const int z = blockIdx.z;

    const __nv_bfloat16 *Ah, *Al, *Bh, *Bl;
    if (mode == 0) {
        Ah = g_xh; Al = g_xl;
        Bh = g_wh + (size_t)z * C_ * C_; Bl = g_wl + (size_t)z * C_ * C_;
    } else {
        Ah = g_oh; Al = g_ol;
        Bh = g_wh + (size_t)3 * C_ * C_; Bl = g_wl + (size_t)3 * C_ * C_;
    }

    const int prow = tid >> 2;            // 0..63
    const int pseg = (tid & 3) * 8;       // bf16 offset within 32

    wmma::fragment<wmma::accumulator, 16, 16, 16, float> acc[4][2];
#pragma unroll
    for (int i = 0; i < 4; i++)
#pragma unroll
        for (int j = 0; j < 2; j++) wmma::fill_fragment(acc[i][j], 0.f);

    auto issue = [&](int ch, int s) {
        const int koff = ch * 32 + pseg;
#pragma unroll
        for (int it = 0; it < 2; it++) {
            const int row = prow + it * 64;
            const uint32_t d = sb + s * TCB + (row * TSTR + pseg) * 2;
            CP16(d +     0, Ah + (size_t)(i0 + row) * C_ + koff);
            CP16(d + 10240, Al + (size_t)(i0 + row) * C_ + koff);
            CP16(d + 20480, Bh + (size_t)(j0 + row) * C_ + koff);
            CP16(d + 30720, Bl + (size_t)(j0 + row) * C_ + koff);
        }
        CP_COMMIT();
    };

    issue(0, 0);
    for (int ch = 0; ch < C_ / 32; ch++) {
        const int s = ch & 1;
        if (ch + 1 < C_ / 32) { issue(ch + 1, (ch + 1) & 1); CP_WAIT1(); }
        else                  { CP_WAIT0(); }
        __syncthreads();

        const __nv_bfloat16* bAh = (const __nv_bfloat16*)(gsm + s * TCB);
        const __nv_bfloat16* bAl = (const __nv_bfloat16*)(gsm + s * TCB + 10240);
        const __nv_bfloat16* bBh = (const __nv_bfloat16*)(gsm + s * TCB + 20480);
        const __nv_bfloat16* bBl = (const __nv_bfloat16*)(gsm + s * TCB + 30720);

        // low-register order: B-pair resident, stream A fragments one at a time
#pragma unroll
        for (int ks = 0; ks < 2; ks++) {
            const int kk = ks * 16;
#pragma unroll
            for (int j = 0; j < 2; j++) {
                const int c = wn * 32 + j * 16;
                wmma::fragment<wmma::matrix_b, 16, 16, 16, __nv_bfloat16, wmma::col_major> fbh, fbl;
                wmma::load_matrix_sync(fbh, &bBh[c * TSTR + kk], TSTR);
                wmma::load_matrix_sync(fbl, &bBl[c * TSTR + kk], TSTR);
#pragma unroll
                for (int i = 0; i < 4; i++) {
                    const int r = wm * 64 + i * 16;
                    wmma::fragment<wmma::matrix_a, 16, 16, 16, __nv_bfloat16, wmma::row_major> fa;
                    wmma::load_matrix_sync(fa, &bAh[r * TSTR + kk], TSTR);
                    wmma::mma_sync(acc[i][j], fa, fbh, acc[i][j]);
                    wmma::mma_sync(acc[i][j], fa, fbl, acc[i][j]);
                    wmma::load_matrix_sync(fa, &bAl[r * TSTR + kk], TSTR);
                    wmma::mma_sync(acc[i][j], fa, fbh, acc[i][j]);
                }
            }
        }
        __syncthreads();
    }

    if (mode == 1) {
#pragma unroll
        for (int i = 0; i < 4; i++) {
            const int row0 = i0 + wm * 64 + i * 16;
#pragma unroll
            for (int j = 0; j < 2; j++) {
                const int col0 = j0 + wn * 32 + j * 16;
                __syncwarp();
                wmma::store_matrix_sync(&stage[w][0], acc[i][j], 16, wmma::mem_row_major);
                __syncwarp();
#pragma unroll
                for (int half = 0; half < 2; half++) {
                    const int r = half * 8 + (lid >> 2);
                    const int c4 = (lid & 3) * 4;
                    float4 v4 = *(float4*)&stage[w][r * 16 + c4];
                    float4 bv = *(const float4*)(bias + col0 + c4);
                    v4.x += bv.x; v4.y += bv.y; v4.z += bv.z; v4.w += bv.w;
                    *(float4*)(outC + (size_t)(row0 + r) * C_ + col0 + c4) = v4;
                }
            }
        }
        return;
    }

    // mode 0 epilogue: stage fragments, vectorized scatter to per-head splits
#pragma unroll
    for (int i = 0; i < 4; i++) {
        const int row0 = i0 + wm * 64 + i * 16;
#pragma unroll
        for (int j = 0; j < 2; j++) {
            const int col0 = j0 + wn * 32 + j * 16;
            __syncwarp();
            wmma::store_matrix_sync(&stage[w][0], acc[i][j], 16, wmma::mem_row_major);
            __syncwarp();
#pragma unroll
            for (int half = 0; half < 2; half++) {
                const int r = half * 8 + (lid >> 2);
                const int c4 = (lid & 3) * 4;
                float4 v4 = *(float4*)&stage[w][r * 16 + c4];
                const int grow = row0 + r;
                const int gcol = col0 + c4;                  // 4-col group, never crosses head
                const int b = grow / N_;
                const int n = grow % N_;
                const int h = gcol / D_;
                const int d = gcol % D_;
                const size_t dst = ((size_t)(b * H_ + h) * N_ + n) * D_ + d;
                if (z == 0) {
                    v4.x *= SCALE_; v4.y *= SCALE_; v4.z *= SCALE_; v4.w *= SCALE_;
                }
                const uint32_t h01 = pack_bf16x2(v4.x, v4.y);
                const uint32_t h23 = pack_bf16x2(v4.z, v4.w);
                const uint32_t l01 = pack_bf16x2(v4.x - bfx2_lo(h01), v4.y - bfx2_hi(h01));
                const uint32_t l23 = pack_bf16x2(v4.z - bfx2_lo(h23), v4.w - bfx2_hi(h23));
                __nv_bfloat16 *ph, *pl;
                if (z == 0)      { ph = g_qh; pl = g_ql; }
                else if (z == 1) { ph = g_kh; pl = g_kl; }
                else             { ph = g_vh; pl = g_vl; *(float4*)(out_v + dst) = v4; }
                *(uint2*)(ph + dst) = make_uint2(h01, h23);
                *(uint2*)(pl + dst) = make_uint2(l01, l23);
            }
        }
    }
}

// ================ QK^T wmma GEMM -> E = exp(score) + partial row sums =======
// QSTR=56: 112B row stride -> 16B-aligned uint4 stores AND conflict-free LDSM
// N_=784 is a multiple of 16, so every 16x16 tile is fully in- or out-of-range.
#define QSTR 56
#define QTB (128 * QSTR * 2)            // 14336 bytes per tile
#define QK_SMEM (4 * QTB)               // 57344

__global__ void __launch_bounds__(256, 2) qk_gemm(float* __restrict__ attn) {
    extern __shared__ char qsm[];
    __nv_bfloat16* sQh = (__nv_bfloat16*)qsm;
    __nv_bfloat16* sQl = (__nv_bfloat16*)(qsm + QTB);
    __nv_bfloat16* sKh = (__nv_bfloat16*)(qsm + 2 * QTB);
    __nv_bfloat16* sKl = (__nv_bfloat16*)(qsm + 3 * QTB);
    float (*stage)[256] = (float(*)[256])qsm;          // overlay (post-mma)
    float* partial = (float*)(qsm + 49152);            // [4][128] overlay

    const int tid = threadIdx.x;
    const int w = tid >> 5;
    const int lid = tid & 31;
    const int wm = w & 1;
    const int wn = w >> 1;
    const int m0 = blockIdx.x * 128;
    const int n0 = blockIdx.y * 128;
    const int bh = blockIdx.z;

    const __nv_bfloat16* qb = g_qh + (size_t)bh * N_ * D_;
    const __nv_bfloat16* qlb = g_ql + (size_t)bh * N_ * D_;
    const __nv_bfloat16* kb = g_kh + (size_t)bh * N_ * D_;
    const __nv_bfloat16* klb = g_kl + (size_t)bh * N_ * D_;

#pragma unroll
    for (int it = 0; it < 3; it++) {
        const int v = tid + it * 256;
        const int row = v / 6;
        const int seg = (v % 6) * 8;
        const int qrow = min(n0 + row, N_ - 1);
        const int krow = min(m0 + row, N_ - 1);
        const int dst = row * QSTR + seg;
        *(uint4*)&sQh[dst] = *(const uint4*)(qb + (size_t)qrow * D_ + seg);
        *(uint4*)&sQl[dst] = *(const uint4*)(qlb + (size_t)qrow * D_ + seg);
        *(uint4*)&sKh[dst] = *(const uint4*)(kb + (size_t)krow * D_ + seg);
        *(uint4*)&sKl[dst] = *(const uint4*)(klb + (size_t)krow * D_ + seg);
    }
    __syncthreads();

    wmma::fragment<wmma::accumulator, 16, 16, 16, float> acc[4][2];
#pragma unroll
    for (int i = 0; i < 4; i++)
#pragma unroll
        for (int j = 0; j < 2; j++) wmma::fill_fragment(acc[i][j], 0.f);

#pragma unroll
    for (int ks = 0; ks < 3; ks++) {
        const int kk = ks * 16;
#pragma unroll
        for (int j = 0; j < 2; j++) {
            const int c = wn * 32 + j * 16;
            wmma::fragment<wmma::matrix_b, 16, 16, 16, __nv_bfloat16, wmma::col_major> fbh, fbl;
            wmma::load_matrix_sync(fbh, &sKh[c * QSTR + kk], QSTR);
            wmma::load_matrix_sync(fbl, &sKl[c * QSTR + kk], QSTR);
#pragma unroll
            for (int i = 0; i < 4; i++) {
                const int r = wm * 64 + i * 16;
                wmma::fragment<wmma::matrix_a, 16, 16, 16, __nv_bfloat16, wmma::row_major> fa;
                wmma::load_matrix_sync(fa, &sQh[r * QSTR + kk], QSTR);
                wmma::mma_sync(acc[i][j], fa, fbh, acc[i][j]);
                wmma::mma_sync(acc[i][j], fa, fbl, acc[i][j]);
                wmma::load_matrix_sync(fa, &sQl[r * QSTR + kk], QSTR);
                wmma::mma_sync(acc[i][j], fa, fbh, acc[i][j]);
            }
        }
    }

    __syncthreads();   // smem tiles -> stage/partial overlay

    float* abase = attn + (size_t)bh * N_ * N_;
#pragma unroll
    for (int i = 0; i < 4; i++) {
        const int row0 = n0 + wm * 64 + i * 16;
        const bool rowok = (row0 < N_);
        float rs[2] = {0.f, 0.f};
#pragma unroll
        for (int j = 0; j < 2; j++) {
            const int col0 = m0 + wn * 32 + j * 16;
            const bool colok = (col0 < N_);
            __syncwarp();
            wmma::store_matrix_sync(&stage[w][0], acc[i][j], 16, wmma::mem_row_major);
            __syncwarp();
            if (colok) {
#pragma unroll
                for (int half = 0; half < 2; half++) {
                    const int r = half * 8 + (lid >> 2);
                    const int c4 = (lid & 3) * 4;
                    float4 sv = *(float4*)&stage[w][r * 16 + c4];
                    float4 ev;
                    ev.x = __expf(sv.x); ev.y = __expf(sv.y);
                    ev.z = __expf(sv.z); ev.w = __expf(sv.w);
                    rs[half] += ev.x + ev.y + ev.z + ev.w;
                    if (rowok)
                        *(float4*)(abase + (size_t)(row0 + r) * N_ + col0 + c4) = ev;
                }
            }
        }
        // reduce across the 4 column-group lanes (lid&3), leaders write partial
#pragma unroll
        for (int half = 0; half < 2; half++) {
            float v = rs[half];
            v += __shfl_xor_sync(0xffffffffu, v, 1);
            v += __shfl_xor_sync(0xffffffffu, v, 2);
            if ((lid & 3) == 0) {
                const int rl = wm * 64 + i * 16 + half * 8 + (lid >> 2);
                partial[wn * 128 + rl] = v;
            }
        }
    }
    __syncthreads();
    if (tid < 128) {
        const int n = n0 + tid;
        if (n < N_) {
            g_psum[((size_t)bh * 7 + blockIdx.x) * N_ + n] =
                partial[tid] + partial[128 + tid] + partial[256 + tid] + partial[384 + tid];
        }
    }
}

// ======== fused: finalize attn ((1-g)E/S + g*pos) + AV + o-split ============
// grid (stripe 7, b 8, h 16) so blocks sharing pos[h] are adjacent (L2 reuse).
#define FAV_SMEM (2 * 112 * 120 * 2 + 448 + 7 * 256 * 4)   // 61376

__global__ void __launch_bounds__(256) fused_av(const float* __restrict__ gating,
                                                float* __restrict__ attn) {
    extern __shared__ char fsm[];
    __nv_bfloat16* sAh = (__nv_bfloat16*)fsm;                  // [112][120]
    __nv_bfloat16* sAl = (__nv_bfloat16*)(fsm + 26880);
    float* scoef = (float*)(fsm + 53760);                      // [112]
    float (*ostage)[256] = (float(*)[256])(fsm + 54208);       // [7][256]

    const int tid = threadIdx.x;
    const int w = tid >> 5;
    const int lid = tid & 31;
    const int b = blockIdx.y;
    const int h = blockIdx.z;
    const int bh = b * H_ + h;
    const int r0 = blockIdx.x * 112;

    const float g = 1.f / (1.f + __expf(-gating[h]));

    for (int row = tid; row < 112; row += 256) {
        float S = 0.f;
#pragma unroll
        for (int mb = 0; mb < 7; mb++)
            S += g_psum[((size_t)bh * 7 + mb) * N_ + r0 + row];
        scoef[row] = (1.f - g) / S;
    }
    __syncthreads();

    float* abase = attn + (size_t)bh * N_ * N_;
    const float* pbase = g_pos + (size_t)h * N_ * N_;
    const __nv_bfloat16* vhb = g_vh + (size_t)bh * N_ * D_;
    const __nv_bfloat16* vlb = g_vl + (size_t)bh * N_ * D_;

    wmma::fragment<wmma::accumulator, 16, 16, 16, float> acc[3];
#pragma unroll
    for (int j = 0; j < 3; j++) wmma::fill_fragment(acc[j], 0.f);

    for (int c = 0; c < 7; c++) {
        const int m0 = c * 112;
        for (int v = tid; v < 112 * 28; v += 256) {
            const int row = v / 28;
            const int cg = v - row * 28;
            const size_t gidx = (size_t)(r0 + row) * N_ + m0 + cg * 4;
            float4 E = *(const float4*)(abase + gidx);
            float4 p = *(const float4*)(pbase + gidx);
            const float cf = scoef[row];
            float4 a;
            a.x = cf * E.x + g * p.x;
            a.y = cf * E.y + g * p.y;
            a.z = cf * E.z + g * p.z;
            a.w = cf * E.w + g * p.w;
            *(float4*)(abase + gidx) = a;
            uint32_t h01 = pack_bf16x2(a.x, a.y);
            uint32_t h23 = pack_bf16x2(a.z, a.w);
            uint32_t l01 = pack_bf16x2(a.x - bfx2_lo(h01), a.y - bfx2_hi(h01));
            uint32_t l23 = pack_bf16x2(a.z - bfx2_lo(h23), a.w - bfx2_hi(h23));
            const int so = row * 120 + cg * 4;
            *(uint2*)&sAh[so] = make_uint2(h01, h23);
            *(uint2*)&sAl[so] = make_uint2(l01, l23);
        }
        __syncthreads();

        if (w < 7) {
#pragma unroll
            for (int kt = 0; kt < 7; kt++) {
                wmma::fragment<wmma::matrix_a, 16, 16, 16, __nv_bfloat16, wmma::row_major> fah, fal;
                wmma::load_matrix_sync(fah, &sAh[(w * 16) * 120 + kt * 16], 120);
                wmma::load_matrix_sync(fal, &sAl[(w * 16) * 120 + kt * 16], 120);
#pragma unroll
                for (int j = 0; j < 3; j++) {
                    wmma::fragment<wmma::matrix_b, 16, 16, 16, __nv_bfloat16, wmma::row_major> fbh, fbl;
                    wmma::load_matrix_sync(fbh, vhb + (size_t)(m0 + kt * 16) * D_ + j * 16, D_);
                    wmma::load_matrix_sync(fbl, vlb + (size_t)(m0 + kt * 16) * D_ + j * 16, D_);
                    wmma::mma_sync(acc[j], fah, fbh, acc[j]);
                    wmma::mma_sync(acc[j], fah, fbl, acc[j]);
                    wmma::mma_sync(acc[j], fal, fbh, acc[j]);
                }
            }
        }
        __syncthreads();
    }

    if (w < 7) {
#pragma unroll
        for (int j = 0; j < 3; j++) {
            __syncwarp();
            wmma::store_matrix_sync(&ostage[w][0], acc[j], 16, wmma::mem_row_major);
            __syncwarp();
#pragma unroll
            for (int tt = 0; tt < 8; tt++) {
                const int idx = tt * 32 + lid;
                const float v = ostage[w][idx];
                const int row = r0 + w * 16 + (idx >> 4);
                const int col = h * D_ + j * 16 + (idx & 15);
                const size_t dst = (size_t)(b * N_ + row) * C_ + col;
                __nv_bfloat16 hi = __float2bfloat16(v);
                g_oh[dst] = hi;
                g_ol[dst] = __float2bfloat16(v - __bfloat162float(hi));
            }
        }
    }
}

// ---------------- launch ----------------------------------------------------
extern "C" void kernel_launch(void* const* d_in, const int* in_sizes, int n_in,
                              void* d_out, int out_size) {
    const float* x      = (const float*)d_in[0];
    const float* Wq     = (const float*)d_in[1];
    const float* Wk     = (const float*)d_in[2];
    const float* Wv     = (const float*)d_in[3];
    const float* Wproj  = (const float*)d_in[4];
    const float* b_proj = (const float*)d_in[5];
    const float* W_pos  = (const float*)d_in[6];
    const float* b_pos  = (const float*)d_in[7];
    const float* gating = (const float*)d_in[8];

    float* out_o    = (float*)d_out;                              // [B,N,C]
    float* out_attn = out_o + (size_t)B_ * N_ * C_;               // [B,H,N,N]
    float* out_v    = out_attn + (size_t)B_ * H_ * N_ * N_;       // [B,H,N,D]

    cudaFuncSetAttribute((const void*)tc_gemm,
                         cudaFuncAttributeMaxDynamicSharedMemorySize, TC_SMEM);
    cudaFuncSetAttribute((const void*)qk_gemm,
                         cudaFuncAttributeMaxDynamicSharedMemorySize, QK_SMEM);
    cudaFuncSetAttribute((const void*)fused_av,
                         cudaFuncAttributeMaxDynamicSharedMemorySize, FAV_SMEM);

    split_x<<<(M_ * C_ / 4 + 255) / 256, 256>>>(x);                            // 0
    split_w<<<dim3((C_ * C_ / 4 + 255) / 256, 4), 256>>>(Wq, Wk, Wv, Wproj);   // 1
    tc_gemm<<<dim3(C_ / 128, M_ / 128, 3), 256, TC_SMEM>>>(0, nullptr, out_v, nullptr); // 2
    qk_gemm<<<dim3(7, 7, BH_), 256, QK_SMEM>>>(out_attn);                      // 3 <- profiled
    pos_kernel<<<dim3(98, H_), 256>>>(W_pos, b_pos);                           // 4
    fused_av<<<dim3(7, B_, H_), 256, FAV_SMEM>>>(gating, out_attn);            // 5
    tc_gemm<<<dim3(C_ / 128, M_ / 128, 1), 256, TC_SMEM>>>(1, out_o, nullptr, b_proj);  // 6
}